// round 8
// baseline (speedup 1.0000x reference)
#include <cuda_runtime.h>

// VolumeRenderer: B=4, HW=65536, N=48
// inputs: rgb (B,HW,N,3) f32, sigma (B,HW,N,1) f32, z_vals (B,HW,N) f32
// output: rgb_map (B*HW,3) then depth_map (B*HW), concatenated f32.
//
// 16 lanes <-> 16 samples; warp = 2 rays per pair, 2 pairs per warp,
// software-pipelined. __launch_bounds__(256,4) gives a 64-reg budget so
// pair B's 30 loads stay hoisted above pair A's compute (regs=32 in the
// previous build proved ptxas sank them). Transpose-reduce epilogue:
// 10 shuffles instead of 16, stores from 4 adjacent lanes.

#define TOTAL_RAYS (4 * 65536)   // 262144
#define NSAMP      48
#define RAYS_PB    32            // 256 threads = 8 warps x 4 rays

#define FULLM 0xffffffffu

struct RayVals {
    float z0, z1, z2, s0, s1, s2;
    float r0, g0, b0, r1, g1, b1, r2, g2, b2;
};

__device__ __forceinline__ RayVals load_ray(
    const float* __restrict__ rgb, const float* __restrict__ sigma,
    const float* __restrict__ z_vals, int ray, int sub)
{
    const size_t zb = (size_t)ray * NSAMP;
    const size_t rb = (size_t)ray * (NSAMP * 3);
    RayVals v;
    v.z0 = z_vals[zb +  0 + sub];
    v.z1 = z_vals[zb + 16 + sub];
    v.z2 = z_vals[zb + 32 + sub];
    v.s0 = sigma [zb +  0 + sub];
    v.s1 = sigma [zb + 16 + sub];
    v.s2 = sigma [zb + 32 + sub];
    v.r0 = rgb[rb + ( 0 + sub) * 3 + 0];
    v.g0 = rgb[rb + ( 0 + sub) * 3 + 1];
    v.b0 = rgb[rb + ( 0 + sub) * 3 + 2];
    v.r1 = rgb[rb + (16 + sub) * 3 + 0];
    v.g1 = rgb[rb + (16 + sub) * 3 + 1];
    v.b1 = rgb[rb + (16 + sub) * 3 + 2];
    v.r2 = rgb[rb + (32 + sub) * 3 + 0];
    v.g2 = rgb[rb + (32 + sub) * 3 + 1];
    v.b2 = rgb[rb + (32 + sub) * 3 + 2];
    return v;
}

__device__ __forceinline__ void compute_ray(
    const RayVals& v, int ray, int sub, float* __restrict__ out)
{
    // per-sample distances (z_{i+1} - z_i; last capped at 1e10)
    float z1f = __shfl_sync(FULLM, v.z1, 0, 16);
    float z2f = __shfl_sync(FULLM, v.z2, 0, 16);
    float zn0 = __shfl_down_sync(FULLM, v.z0, 1, 16);
    float zn1 = __shfl_down_sync(FULLM, v.z1, 1, 16);
    float zn2 = __shfl_down_sync(FULLM, v.z2, 1, 16);
    float d0 = ((sub == 15) ? z1f : zn0) - v.z0;
    float d1 = ((sub == 15) ? z2f : zn1) - v.z1;
    float d2 = (sub == 15) ? 1e10f : (zn2 - v.z2);

    float carry = 1.0f;
    float pr = 0.f, pg = 0.f, pb = 0.f, pd = 0.f;

#define SEGMENT(ZV, SV, DV, RV, GV, BV)                                   \
    {                                                                     \
        float e = __expf(-(SV) * (DV));                                   \
        float incl = e + 1e-10f;                                          \
        _Pragma("unroll")                                                 \
        for (int k = 1; k < 16; k <<= 1) {                                \
            float u = __shfl_up_sync(FULLM, incl, k, 16);                 \
            if (sub >= k) incl *= u;                                      \
        }                                                                 \
        float v1 = __shfl_up_sync(FULLM, incl, 1, 16);                    \
        float T  = (sub == 0) ? carry : carry * v1;                       \
        float w  = (1.0f - e) * T;                                        \
        pr = fmaf(w, (RV), pr);                                           \
        pg = fmaf(w, (GV), pg);                                           \
        pb = fmaf(w, (BV), pb);                                           \
        pd = fmaf(w, (ZV), pd);                                           \
        carry *= __shfl_sync(FULLM, incl, 15, 16);                        \
    }

    SEGMENT(v.z0, v.s0, d0, v.r0, v.g0, v.b0)
    SEGMENT(v.z1, v.s1, d1, v.r1, v.g1, v.b1)
    SEGMENT(v.z2, v.s2, d2, v.r2, v.g2, v.b2)
#undef SEGMENT

    // ---- transpose-reduce across the 16-lane group (10 shuffles) ----
    // Stage 1: butterflies strides 1,2 on all 4 vars -> every lane holds
    // its 4-lane group's partial sum of each var.
#pragma unroll
    for (int k = 1; k <= 2; k <<= 1) {
        pr += __shfl_xor_sync(FULLM, pr, k, 16);
        pg += __shfl_xor_sync(FULLM, pg, k, 16);
        pb += __shfl_xor_sync(FULLM, pb, k, 16);
        pd += __shfl_xor_sync(FULLM, pd, k, 16);
    }
    // Stage 2: lane selects var (sub&3); butterflies strides 4,8 sum that
    // var across the four 4-lane groups (lanes l, l^4, l^8, l^12 all carry
    // the same var).
    int c = sub & 3;
    float vsel = (c == 0) ? pr : (c == 1) ? pg : (c == 2) ? pb : pd;
    vsel += __shfl_xor_sync(FULLM, vsel, 4, 16);
    vsel += __shfl_xor_sync(FULLM, vsel, 8, 16);

    if (sub < 3) {
        out[(size_t)ray * 3 + sub] = vsel;          // r, g, b from lanes 0..2
    } else if (sub == 3) {
        out[(size_t)TOTAL_RAYS * 3 + ray] = vsel;   // depth from lane 3
    }
}

__global__ __launch_bounds__(256, 4)
void volrend_kernel(const float* __restrict__ rgb,
                    const float* __restrict__ sigma,
                    const float* __restrict__ z_vals,
                    float* __restrict__ out)
{
    const int tid  = threadIdx.x;
    const int warp = tid >> 5;
    const int lane = tid & 31;
    const int sub  = lane & 15;
    const int half = lane >> 4;

    const int base = blockIdx.x * RAYS_PB + warp * 4;
    const int rayA = base + half;
    const int rayB = base + 2 + half;

    // all loads (A then B) before any compute: with the 64-reg budget the
    // B loads stay hoisted and remain in flight across A's scan chain.
    RayVals va = load_ray(rgb, sigma, z_vals, rayA, sub);
    RayVals vb = load_ray(rgb, sigma, z_vals, rayB, sub);

    compute_ray(va, rayA, sub, out);
    compute_ray(vb, rayB, sub, out);
}

extern "C" void kernel_launch(void* const* d_in, const int* in_sizes, int n_in,
                              void* d_out, int out_size)
{
    const float* rgb    = (const float*)d_in[0];
    const float* sigma  = (const float*)d_in[1];
    const float* z_vals = (const float*)d_in[2];
    float* out = (float*)d_out;

    dim3 grid(TOTAL_RAYS / RAYS_PB);   // 8192 blocks
    dim3 block(256);
    volrend_kernel<<<grid, block>>>(rgb, sigma, z_vals, out);
}

// round 10
// speedup vs baseline: 1.0149x; 1.0149x over previous
#include <cuda_runtime.h>

// VolumeRenderer: B=4, HW=65536, N=48
// inputs: rgb (B,HW,N,3) f32, sigma (B,HW,N,1) f32, z_vals (B,HW,N) f32
// output: rgb_map (B*HW,3) then depth_map (B*HW), concatenated f32.
//
// 16 lanes <-> 16 samples; warp = 2 ray-pairs (4 rays), loads for both
// pairs front-batched. ALL SIX inclusive scans (2 pairs x 3 segments) run
// interleaved -> 4-deep shuffle critical path instead of a serialized
// carry chain. Segment coupling applied afterward via incl[15] broadcasts.

#define TOTAL_RAYS (4 * 65536)   // 262144
#define NSAMP      48
#define RAYS_PB    32            // 256 threads = 8 warps x 4 rays

#define FULLM 0xffffffffu

__global__ __launch_bounds__(256, 4)
void volrend_kernel(const float* __restrict__ rgb,
                    const float* __restrict__ sigma,
                    const float* __restrict__ z_vals,
                    float* __restrict__ out)
{
    const int tid  = threadIdx.x;
    const int warp = tid >> 5;
    const int lane = tid & 31;
    const int sub  = lane & 15;
    const int half = lane >> 4;

    const int base = blockIdx.x * RAYS_PB + warp * 4;
    const int rayA = base + half;
    const int rayB = base + 2 + half;

    const size_t zbA = (size_t)rayA * NSAMP, rbA = (size_t)rayA * (NSAMP * 3);
    const size_t zbB = (size_t)rayB * NSAMP, rbB = (size_t)rayB * (NSAMP * 3);

    // ---- front-batch ALL loads for both ray-pairs (30 LDG.32) ----
    float zA0 = z_vals[zbA +  0 + sub], zA1 = z_vals[zbA + 16 + sub], zA2 = z_vals[zbA + 32 + sub];
    float sA0 = sigma [zbA +  0 + sub], sA1 = sigma [zbA + 16 + sub], sA2 = sigma [zbA + 32 + sub];
    float zB0 = z_vals[zbB +  0 + sub], zB1 = z_vals[zbB + 16 + sub], zB2 = z_vals[zbB + 32 + sub];
    float sB0 = sigma [zbB +  0 + sub], sB1 = sigma [zbB + 16 + sub], sB2 = sigma [zbB + 32 + sub];
    float rA0 = rgb[rbA + ( 0 + sub) * 3 + 0], gA0 = rgb[rbA + ( 0 + sub) * 3 + 1], bA0 = rgb[rbA + ( 0 + sub) * 3 + 2];
    float rA1 = rgb[rbA + (16 + sub) * 3 + 0], gA1 = rgb[rbA + (16 + sub) * 3 + 1], bA1 = rgb[rbA + (16 + sub) * 3 + 2];
    float rA2 = rgb[rbA + (32 + sub) * 3 + 0], gA2 = rgb[rbA + (32 + sub) * 3 + 1], bA2 = rgb[rbA + (32 + sub) * 3 + 2];
    float rB0 = rgb[rbB + ( 0 + sub) * 3 + 0], gB0 = rgb[rbB + ( 0 + sub) * 3 + 1], bB0 = rgb[rbB + ( 0 + sub) * 3 + 2];
    float rB1 = rgb[rbB + (16 + sub) * 3 + 0], gB1 = rgb[rbB + (16 + sub) * 3 + 1], bB1 = rgb[rbB + (16 + sub) * 3 + 2];
    float rB2 = rgb[rbB + (32 + sub) * 3 + 0], gB2 = rgb[rbB + (32 + sub) * 3 + 1], bB2 = rgb[rbB + (32 + sub) * 3 + 2];

    // ---- distances (independent shuffles) ----
    float zA1f = __shfl_sync(FULLM, zA1, 0, 16);
    float zA2f = __shfl_sync(FULLM, zA2, 0, 16);
    float zB1f = __shfl_sync(FULLM, zB1, 0, 16);
    float zB2f = __shfl_sync(FULLM, zB2, 0, 16);
    float nA0 = __shfl_down_sync(FULLM, zA0, 1, 16);
    float nA1 = __shfl_down_sync(FULLM, zA1, 1, 16);
    float nA2 = __shfl_down_sync(FULLM, zA2, 1, 16);
    float nB0 = __shfl_down_sync(FULLM, zB0, 1, 16);
    float nB1 = __shfl_down_sync(FULLM, zB1, 1, 16);
    float nB2 = __shfl_down_sync(FULLM, zB2, 1, 16);
    bool last = (sub == 15);
    float dA0 = (last ? zA1f : nA0) - zA0;
    float dA1 = (last ? zA2f : nA1) - zA1;
    float dA2 = last ? 1e10f : (nA2 - zA2);
    float dB0 = (last ? zB1f : nB0) - zB0;
    float dB1 = (last ? zB2f : nB1) - zB1;
    float dB2 = last ? 1e10f : (nB2 - zB2);

    // ---- per-sample opacities (6 independent exps) ----
    float eA0 = __expf(-sA0 * dA0), eA1 = __expf(-sA1 * dA1), eA2 = __expf(-sA2 * dA2);
    float eB0 = __expf(-sB0 * dB0), eB1 = __expf(-sB1 * dB1), eB2 = __expf(-sB2 * dB2);

    // ---- SIX interleaved inclusive multiplicative scans (depth 4) ----
    float t0 = eA0 + 1e-10f, t1 = eA1 + 1e-10f, t2 = eA2 + 1e-10f;
    float t3 = eB0 + 1e-10f, t4 = eB1 + 1e-10f, t5 = eB2 + 1e-10f;
#pragma unroll
    for (int k = 1; k < 16; k <<= 1) {
        float u0 = __shfl_up_sync(FULLM, t0, k, 16);
        float u1 = __shfl_up_sync(FULLM, t1, k, 16);
        float u2 = __shfl_up_sync(FULLM, t2, k, 16);
        float u3 = __shfl_up_sync(FULLM, t3, k, 16);
        float u4 = __shfl_up_sync(FULLM, t4, k, 16);
        float u5 = __shfl_up_sync(FULLM, t5, k, 16);
        if (sub >= k) { t0 *= u0; t1 *= u1; t2 *= u2; t3 *= u3; t4 *= u4; t5 *= u5; }
    }

    // ---- segment coupling: totals of seg0/seg1 per ray ----
    float cA1 = __shfl_sync(FULLM, t0, 15, 16);
    float cA2 = cA1 * __shfl_sync(FULLM, t1, 15, 16);
    float cB1 = __shfl_sync(FULLM, t3, 15, 16);
    float cB2 = cB1 * __shfl_sync(FULLM, t4, 15, 16);

    // ---- exclusive transmittance per segment ----
    float xA0 = __shfl_up_sync(FULLM, t0, 1, 16);
    float xA1 = __shfl_up_sync(FULLM, t1, 1, 16);
    float xA2 = __shfl_up_sync(FULLM, t2, 1, 16);
    float xB0 = __shfl_up_sync(FULLM, t3, 1, 16);
    float xB1 = __shfl_up_sync(FULLM, t4, 1, 16);
    float xB2 = __shfl_up_sync(FULLM, t5, 1, 16);
    bool first = (sub == 0);
    float TA0 = first ? 1.0f : xA0;
    float TA1 = cA1 * (first ? 1.0f : xA1);
    float TA2 = cA2 * (first ? 1.0f : xA2);
    float TB0 = first ? 1.0f : xB0;
    float TB1 = cB1 * (first ? 1.0f : xB1);
    float TB2 = cB2 * (first ? 1.0f : xB2);

    // ---- weights and accumulation ----
    float wA0 = (1.0f - eA0) * TA0, wA1 = (1.0f - eA1) * TA1, wA2 = (1.0f - eA2) * TA2;
    float wB0 = (1.0f - eB0) * TB0, wB1 = (1.0f - eB1) * TB1, wB2 = (1.0f - eB2) * TB2;

    float prA = fmaf(wA2, rA2, fmaf(wA1, rA1, wA0 * rA0));
    float pgA = fmaf(wA2, gA2, fmaf(wA1, gA1, wA0 * gA0));
    float pbA = fmaf(wA2, bA2, fmaf(wA1, bA1, wA0 * bA0));
    float pdA = fmaf(wA2, zA2, fmaf(wA1, zA1, wA0 * zA0));
    float prB = fmaf(wB2, rB2, fmaf(wB1, rB1, wB0 * rB0));
    float pgB = fmaf(wB2, gB2, fmaf(wB1, gB1, wB0 * gB0));
    float pbB = fmaf(wB2, bB2, fmaf(wB1, bB1, wB0 * bB0));
    float pdB = fmaf(wB2, zB2, fmaf(wB1, zB1, wB0 * zB0));

    // ---- transpose-reduce both rays (interleaved, independent chains) ----
#pragma unroll
    for (int k = 1; k <= 2; k <<= 1) {
        prA += __shfl_xor_sync(FULLM, prA, k, 16);
        pgA += __shfl_xor_sync(FULLM, pgA, k, 16);
        pbA += __shfl_xor_sync(FULLM, pbA, k, 16);
        pdA += __shfl_xor_sync(FULLM, pdA, k, 16);
        prB += __shfl_xor_sync(FULLM, prB, k, 16);
        pgB += __shfl_xor_sync(FULLM, pgB, k, 16);
        pbB += __shfl_xor_sync(FULLM, pbB, k, 16);
        pdB += __shfl_xor_sync(FULLM, pdB, k, 16);
    }
    int c = sub & 3;
    float vA = (c == 0) ? prA : (c == 1) ? pgA : (c == 2) ? pbA : pdA;
    float vB = (c == 0) ? prB : (c == 1) ? pgB : (c == 2) ? pbB : pdB;
    vA += __shfl_xor_sync(FULLM, vA, 4, 16);
    vB += __shfl_xor_sync(FULLM, vB, 4, 16);
    vA += __shfl_xor_sync(FULLM, vA, 8, 16);
    vB += __shfl_xor_sync(FULLM, vB, 8, 16);

    if (sub < 3) {
        out[(size_t)rayA * 3 + sub] = vA;
        out[(size_t)rayB * 3 + sub] = vB;
    } else if (sub == 3) {
        out[(size_t)TOTAL_RAYS * 3 + rayA] = vA;
        out[(size_t)TOTAL_RAYS * 3 + rayB] = vB;
    }
}

extern "C" void kernel_launch(void* const* d_in, const int* in_sizes, int n_in,
                              void* d_out, int out_size)
{
    const float* rgb    = (const float*)d_in[0];
    const float* sigma  = (const float*)d_in[1];
    const float* z_vals = (const float*)d_in[2];
    float* out = (float*)d_out;

    dim3 grid(TOTAL_RAYS / RAYS_PB);   // 8192 blocks
    dim3 block(256);
    volrend_kernel<<<grid, block>>>(rgb, sigma, z_vals, out);
}